// round 10
// baseline (speedup 1.0000x reference)
#include <cuda_runtime.h>
#include <cuda_bf16.h>

// RobustPrompt_I: graph prompt + edge pruning
//  in: x[N,128] f32, edge_index[2,E] i32, p_sim[1,128], p_deg[1,128], p_other[1,128]
//  out: x_new[N,128] f32  ++  keep[E] (0/1 as f32)

#define D        128
#define D4       32
#define NCAP     131072
#define ECAP     1048576
#define SIM_THR  0.2f
#define DEG_THR  3.0f
#define PT_THR   0.1f
#define EPSV     1e-8f

#define NBE      2048        // persistent edge blocks in big_kernel

// packed per-node record:
//  phase 1 (after big_kernel):  [0] = (csum, deg, 0, 0)   [1] = (d0, d1, d2, ||x||^2)
//  phase 2 (after combo2):      [0] = (H0, H1, H2, s)     [1] = (U0, U1, U2, combo-bits)
__device__ float4 g_rec[NCAP][2];
__device__ float  g_dot[ECAP];     // raw dot(x_r, x_c) per edge
__device__ float  g_W[4][4];       // combo -> weight triple over prompts (row=float4)
__device__ float  g_GC[4][4];      // delta_a · delta_b LUT
__device__ float  g_GV[4][4];      // G · W[c] per combo (row=float4)
__device__ float4 g_delta[4][D4];  // the 4 possible delta rows

// ---------- setup body (1 warp): nz flags, Gram, weights, delta rows, LUTs ----------
__device__ __forceinline__ void setup_body(const float* __restrict__ ps,
                                           const float* __restrict__ pd,
                                           const float* __restrict__ po,
                                           int lane) {
    unsigned full = 0xFFFFFFFFu;
    float4 P[3];
    P[0] = reinterpret_cast<const float4*>(ps)[lane];
    P[1] = reinterpret_cast<const float4*>(pd)[lane];
    P[2] = reinterpret_cast<const float4*>(po)[lane];

    int nz[3];
    #pragma unroll
    for (int k = 0; k < 3; k++) {
        bool z = (P[k].x != 0.f) & (P[k].y != 0.f) & (P[k].z != 0.f) & (P[k].w != 0.f);
        nz[k] = __all_sync(full, z);
    }
    float G[3][3];
    #pragma unroll
    for (int a = 0; a < 3; a++)
        #pragma unroll
        for (int b = 0; b < 3; b++) {
            float s = P[a].x * P[b].x + P[a].y * P[b].y + P[a].z * P[b].z + P[a].w * P[b].w;
            #pragma unroll
            for (int o = 16; o > 0; o >>= 1) s += __shfl_xor_sync(full, s, o);
            G[a][b] = s;
        }
    float W[4][3];
    #pragma unroll
    for (int idx = 0; idx < 4; idx++) {
        int msim = idx & 1, mdeg = (idx >> 1) & 1, moth = (idx == 0);
        int plen = msim * nz[0] + mdeg * nz[1] + moth * nz[2];
        float inv = (plen > 0) ? (1.0f / (float)plen) : 0.0f;
        W[idx][0] = (float)msim * inv;
        W[idx][1] = (float)mdeg * inv;
        W[idx][2] = (float)moth * inv;
        float4 dl;
        dl.x = W[idx][0]*P[0].x + W[idx][1]*P[1].x + W[idx][2]*P[2].x;
        dl.y = W[idx][0]*P[0].y + W[idx][1]*P[1].y + W[idx][2]*P[2].y;
        dl.z = W[idx][0]*P[0].z + W[idx][1]*P[1].z + W[idx][2]*P[2].z;
        dl.w = W[idx][0]*P[0].w + W[idx][1]*P[1].w + W[idx][2]*P[2].w;
        g_delta[idx][lane] = dl;
    }
    if (lane == 0) {
        for (int idx = 0; idx < 4; idx++) {
            g_W[idx][0] = W[idx][0]; g_W[idx][1] = W[idx][1];
            g_W[idx][2] = W[idx][2]; g_W[idx][3] = 0.f;
            // G·W[idx]
            for (int k = 0; k < 3; k++)
                g_GV[idx][k] = G[k][0]*W[idx][0] + G[k][1]*W[idx][1] + G[k][2]*W[idx][2];
            g_GV[idx][3] = 0.f;
        }
        for (int a = 0; a < 4; a++)
            for (int b = 0; b < 4; b++) {
                float s = 0.f;
                for (int k = 0; k < 3; k++)
                    for (int j = 0; j < 3; j++)
                        s += W[a][k] * G[k][j] * W[b][j];
                g_GC[a][b] = s;
            }
    }
}

// ---------- K1: edges (pipelined gather+dot+norms+scatter) | setup | node stats ----------
__global__ void big_kernel(const float* __restrict__ x,
                           const int* __restrict__ ei,
                           const float* __restrict__ ps,
                           const float* __restrict__ pd,
                           const float* __restrict__ po,
                           int n, int E) {
    const float4* X = reinterpret_cast<const float4*>(x);
    int bid = blockIdx.x;
    if (bid < NBE) {
        int sub     = threadIdx.x & 7;
        int group   = bid * 32 + (threadIdx.x >> 3);
        int ngroups = NBE * 32;

        int e = group;
        int r = 0, c = 0;
        if (e < E) { r = __ldg(&ei[e]); c = __ldg(&ei[E + e]); }
        while (e < E) {
            const float4* Ar = X + (size_t)r * D4 + sub;
            const float4* Bc = X + (size_t)c * D4 + sub;
            float4 a[4], b[4];
            #pragma unroll
            for (int k = 0; k < 4; k++) a[k] = __ldg(Ar + 8 * k);
            #pragma unroll
            for (int k = 0; k < 4; k++) b[k] = __ldg(Bc + 8 * k);

            int en = e + ngroups;
            int rn = 0, cn = 0;
            if (en < E) { rn = __ldg(&ei[en]); cn = __ldg(&ei[E + en]); }

            float s = 0.f, nr = 0.f, nc = 0.f;
            #pragma unroll
            for (int k = 0; k < 4; k++) {
                s  += a[k].x*b[k].x + a[k].y*b[k].y + a[k].z*b[k].z + a[k].w*b[k].w;
                nr += a[k].x*a[k].x + a[k].y*a[k].y + a[k].z*a[k].z + a[k].w*a[k].w;
                nc += b[k].x*b[k].x + b[k].y*b[k].y + b[k].z*b[k].z + b[k].w*b[k].w;
            }
            #pragma unroll
            for (int o = 4; o > 0; o >>= 1) {
                s  += __shfl_xor_sync(0xFFFFFFFFu, s,  o);
                nr += __shfl_xor_sync(0xFFFFFFFFu, nr, o);
                nc += __shfl_xor_sync(0xFFFFFFFFu, nc, o);
            }
            if (sub == 0) {
                g_dot[e] = s;
                float sn = s * rsqrtf(nr) * rsqrtf(nc);
                float* rec = reinterpret_cast<float*>(&g_rec[c][0]);
                atomicAdd(rec,     sn);
                atomicAdd(rec + 1, 1.0f);
            }
            e = en; r = rn; c = cn;
        }
    } else if (bid == NBE) {
        if (threadIdx.x < 32) setup_body(ps, pd, po, threadIdx.x);
    } else {
        int w    = ((bid - NBE - 1) * blockDim.x + threadIdx.x) >> 5;
        int lane = threadIdx.x & 31;
        if (w >= n) return;
        float4 xv = X[(size_t)w * D4 + lane];
        float4 P0 = reinterpret_cast<const float4*>(ps)[lane];
        float4 P1 = reinterpret_cast<const float4*>(pd)[lane];
        float4 P2 = reinterpret_cast<const float4*>(po)[lane];

        float ss = xv.x*xv.x + xv.y*xv.y + xv.z*xv.z + xv.w*xv.w;
        float d0 = xv.x*P0.x + xv.y*P0.y + xv.z*P0.z + xv.w*P0.w;
        float d1 = xv.x*P1.x + xv.y*P1.y + xv.z*P1.z + xv.w*P1.w;
        float d2 = xv.x*P2.x + xv.y*P2.y + xv.z*P2.z + xv.w*P2.w;
        #pragma unroll
        for (int o = 16; o > 0; o >>= 1) {
            ss += __shfl_xor_sync(0xFFFFFFFFu, ss, o);
            d0 += __shfl_xor_sync(0xFFFFFFFFu, d0, o);
            d1 += __shfl_xor_sync(0xFFFFFFFFu, d1, o);
            d2 += __shfl_xor_sync(0xFFFFFFFFu, d2, o);
        }
        if (lane == 0) g_rec[w][1] = make_float4(d0, d1, d2, ss);
    }
}

// ---------- combo2 (thread/node): fold combo + rinv2 into the record ----------
// All per-node transcendentals happen HERE (100k times), not per edge (12.8M).
__global__ void combo2_kernel(int n) {
    int i = blockIdx.x * blockDim.x + threadIdx.x;
    if (i >= n) return;
    float4 cd = g_rec[i][0];   // (csum, deg, 0, 0)
    float4 A  = g_rec[i][1];   // (d0, d1, d2, ||x||^2)
    bool msim = (cd.y > 0.f) && ((cd.x / cd.y) <= SIM_THR);
    bool mdeg = (cd.y <= DEG_THR);
    int c = (int)msim | ((int)mdeg << 1);

    float4 Wc = *reinterpret_cast<const float4*>(&g_W[c][0]);
    float4 Gv = *reinterpret_cast<const float4*>(&g_GV[c][0]);
    float xdd = Wc.x*A.x + Wc.y*A.y + Wc.z*A.z;
    float nn2 = A.w + 2.0f * xdd + g_GC[c][c];
    float s = 1.0f / fmaxf(sqrtf(fmaxf(nn2, 0.f)), EPSV);

    // H = s*(d + 0.5*G*W[c]),  U = s*W[c]
    g_rec[i][0] = make_float4(s * (A.x + 0.5f * Gv.x),
                              s * (A.y + 0.5f * Gv.y),
                              s * (A.z + 0.5f * Gv.z), s);
    g_rec[i][1] = make_float4(s * Wc.x, s * Wc.y, s * Wc.z, __int_as_float(c));
}

// ---------- K2 finish: node write (MLP4) | edge2 (pure gather+FMA) ----------
__global__ void finish_kernel(const float* __restrict__ x,
                              const int* __restrict__ ei,
                              float* __restrict__ out,
                              float* __restrict__ keep,
                              int n, int E, int NBn) {
    if ((int)blockIdx.x < NBn) {
        int tid  = threadIdx.x;
        int node = blockIdx.x * 32 + (tid >> 3);
        if (node >= n) return;
        int j = tid & 7;
        int idx = __float_as_int(g_rec[node][1].w);
        const float4* Xr = reinterpret_cast<const float4*>(x) + (size_t)node * D4;
        float4 xv0 = __ldcs(Xr + j);
        float4 xv1 = __ldcs(Xr + j + 8);
        float4 xv2 = __ldcs(Xr + j + 16);
        float4 xv3 = __ldcs(Xr + j + 24);
        float4 dl0 = g_delta[idx][j];
        float4 dl1 = g_delta[idx][j + 8];
        float4 dl2 = g_delta[idx][j + 16];
        float4 dl3 = g_delta[idx][j + 24];
        xv0.x += dl0.x; xv0.y += dl0.y; xv0.z += dl0.z; xv0.w += dl0.w;
        xv1.x += dl1.x; xv1.y += dl1.y; xv1.z += dl1.z; xv1.w += dl1.w;
        xv2.x += dl2.x; xv2.y += dl2.y; xv2.z += dl2.z; xv2.w += dl2.w;
        xv3.x += dl3.x; xv3.y += dl3.y; xv3.z += dl3.z; xv3.w += dl3.w;
        float4* Or = reinterpret_cast<float4*>(out) + (size_t)node * D4;
        __stcs(Or + j,      xv0);
        __stcs(Or + j + 8,  xv1);
        __stcs(Or + j + 16, xv2);
        __stcs(Or + j + 24, xv3);
    } else {
        // ---- edge2: 2 edges/thread; cos = (sr*sc)*dot + Hr·Uc + Hc·Ur ----
        int t  = (blockIdx.x - NBn) * blockDim.x + threadIdx.x;
        int e0 = t * 2;
        int e1 = e0 + 1;
        if (e0 >= E) return;
        bool has1 = (e1 < E);

        int r0 = __ldg(&ei[e0]);
        int c0 = __ldg(&ei[E + e0]);
        int r1 = has1 ? __ldg(&ei[e1]) : r0;
        int c1 = has1 ? __ldg(&ei[E + e1]) : c0;
        float dt0 = g_dot[e0];
        float dt1 = has1 ? g_dot[e1] : 0.f;

        float4 Hr0 = g_rec[r0][0], Ur0 = g_rec[r0][1];
        float4 Hc0 = g_rec[c0][0], Uc0 = g_rec[c0][1];
        float4 Hr1 = g_rec[r1][0], Ur1 = g_rec[r1][1];
        float4 Hc1 = g_rec[c1][0], Uc1 = g_rec[c1][1];

        float cos0 = (Hr0.w * Hc0.w) * dt0
                   + Hr0.x*Uc0.x + Hr0.y*Uc0.y + Hr0.z*Uc0.z
                   + Hc0.x*Ur0.x + Hc0.y*Ur0.y + Hc0.z*Ur0.z;
        keep[e0] = (cos0 >= PT_THR) ? 1.0f : 0.0f;
        if (has1) {
            float cos1 = (Hr1.w * Hc1.w) * dt1
                       + Hr1.x*Uc1.x + Hr1.y*Uc1.y + Hr1.z*Uc1.z
                       + Hc1.x*Ur1.x + Hc1.y*Ur1.y + Hc1.z*Ur1.z;
            keep[e1] = (cos1 >= PT_THR) ? 1.0f : 0.0f;
        }
    }
}

extern "C" void kernel_launch(void* const* d_in, const int* in_sizes, int n_in,
                              void* d_out, int out_size) {
    const float* x  = (const float*)d_in[0];
    const int*   ei = (const int*)d_in[1];
    const float* ps = (const float*)d_in[2];
    const float* pd = (const float*)d_in[3];
    const float* po = (const float*)d_in[4];
    float* out = (float*)d_out;

    int N = in_sizes[0] / D;
    int E = in_sizes[1] / 2;

    static void* rec_ptr = nullptr;
    if (!rec_ptr) cudaGetSymbolAddress(&rec_ptr, g_rec);
    cudaMemsetAsync(rec_ptr, 0, (size_t)N * 2 * sizeof(float4));

    int NBa = (N + 7) / 8;
    big_kernel<<<NBE + 1 + NBa, 256>>>(x, ei, ps, pd, po, N, E);

    combo2_kernel<<<(N + 255) / 256, 256>>>(N);

    int NBn = (N + 31) / 32;
    bool do_keep = ((long long)out_size >= (long long)N * D + E);
    int NBe2 = do_keep ? ((E + 1) / 2 + 255) / 256 : 0;
    float* keep = out + (size_t)N * D;
    finish_kernel<<<NBn + NBe2, 256>>>(x, ei, out, keep, N, E, NBn);
}

// round 11
// speedup vs baseline: 1.0066x; 1.0066x over previous
#include <cuda_runtime.h>
#include <cuda_bf16.h>

// RobustPrompt_I: graph prompt + edge pruning
//  in: x[N,128] f32, edge_index[2,E] i32, p_sim[1,128], p_deg[1,128], p_other[1,128]
//  out: x_new[N,128] f32  ++  keep[E] (0/1 as f32)

#define D        128
#define D4       32
#define NCAP     131072
#define ECAP     1048576
#define SIM_THR  0.2f
#define DEG_THR  3.0f
#define PT_THR   0.1f
#define EPSV     1e-8f
#define DEG_BIAS 1048576.0   // 2^20: per-edge add = dot*rinv_r + 2^20

#define NBE      2048        // persistent edge blocks in big_kernel

// packed scatter accumulator: csum_scaled + deg*2^20 (one double per node)
__device__ double g_cdpack[NCAP];
// packed per-node record:
//  phase 1 (after big_kernel):  [1] = (d0, d1, d2, ||x||^2)
//  phase 2 (after combo2):      [0] = (H0, H1, H2, s)   [1] = (U0, U1, U2, combo-bits)
__device__ float4 g_rec[NCAP][2];
__device__ float  g_dot[ECAP];     // raw dot(x_r, x_c) per edge
__device__ float  g_W[4][4];       // combo -> weight triple over prompts (row=float4)
__device__ float  g_GC[4][4];      // delta_a · delta_b LUT
__device__ float  g_GV[4][4];      // G · W[c] per combo (row=float4)
__device__ float4 g_delta[4][D4];  // the 4 possible delta rows

// ---------- setup body (1 warp): nz flags, Gram, weights, delta rows, LUTs ----------
__device__ __forceinline__ void setup_body(const float* __restrict__ ps,
                                           const float* __restrict__ pd,
                                           const float* __restrict__ po,
                                           int lane) {
    unsigned full = 0xFFFFFFFFu;
    float4 P[3];
    P[0] = reinterpret_cast<const float4*>(ps)[lane];
    P[1] = reinterpret_cast<const float4*>(pd)[lane];
    P[2] = reinterpret_cast<const float4*>(po)[lane];

    int nz[3];
    #pragma unroll
    for (int k = 0; k < 3; k++) {
        bool z = (P[k].x != 0.f) & (P[k].y != 0.f) & (P[k].z != 0.f) & (P[k].w != 0.f);
        nz[k] = __all_sync(full, z);
    }
    float G[3][3];
    #pragma unroll
    for (int a = 0; a < 3; a++)
        #pragma unroll
        for (int b = 0; b < 3; b++) {
            float s = P[a].x * P[b].x + P[a].y * P[b].y + P[a].z * P[b].z + P[a].w * P[b].w;
            #pragma unroll
            for (int o = 16; o > 0; o >>= 1) s += __shfl_xor_sync(full, s, o);
            G[a][b] = s;
        }
    float W[4][3];
    #pragma unroll
    for (int idx = 0; idx < 4; idx++) {
        int msim = idx & 1, mdeg = (idx >> 1) & 1, moth = (idx == 0);
        int plen = msim * nz[0] + mdeg * nz[1] + moth * nz[2];
        float inv = (plen > 0) ? (1.0f / (float)plen) : 0.0f;
        W[idx][0] = (float)msim * inv;
        W[idx][1] = (float)mdeg * inv;
        W[idx][2] = (float)moth * inv;
        float4 dl;
        dl.x = W[idx][0]*P[0].x + W[idx][1]*P[1].x + W[idx][2]*P[2].x;
        dl.y = W[idx][0]*P[0].y + W[idx][1]*P[1].y + W[idx][2]*P[2].y;
        dl.z = W[idx][0]*P[0].z + W[idx][1]*P[1].z + W[idx][2]*P[2].z;
        dl.w = W[idx][0]*P[0].w + W[idx][1]*P[1].w + W[idx][2]*P[2].w;
        g_delta[idx][lane] = dl;
    }
    if (lane == 0) {
        for (int idx = 0; idx < 4; idx++) {
            g_W[idx][0] = W[idx][0]; g_W[idx][1] = W[idx][1];
            g_W[idx][2] = W[idx][2]; g_W[idx][3] = 0.f;
            for (int k = 0; k < 3; k++)
                g_GV[idx][k] = G[k][0]*W[idx][0] + G[k][1]*W[idx][1] + G[k][2]*W[idx][2];
            g_GV[idx][3] = 0.f;
        }
        for (int a = 0; a < 4; a++)
            for (int b = 0; b < 4; b++) {
                float s = 0.f;
                for (int k = 0; k < 3; k++)
                    for (int j = 0; j < 3; j++)
                        s += W[a][k] * G[k][j] * W[b][j];
                g_GC[a][b] = s;
            }
    }
}

// ---------- K1: edges (dot + row-r norm + single packed atomic) | setup | node stats ----------
__global__ void big_kernel(const float* __restrict__ x,
                           const int* __restrict__ ei,
                           const float* __restrict__ ps,
                           const float* __restrict__ pd,
                           const float* __restrict__ po,
                           int n, int E) {
    const float4* X = reinterpret_cast<const float4*>(x);
    int bid = blockIdx.x;
    if (bid < NBE) {
        int sub     = threadIdx.x & 7;
        int group   = bid * 32 + (threadIdx.x >> 3);
        int ngroups = NBE * 32;

        int e = group;
        int r = 0, c = 0;
        if (e < E) { r = __ldg(&ei[e]); c = __ldg(&ei[E + e]); }
        while (e < E) {
            const float4* Ar = X + (size_t)r * D4 + sub;
            const float4* Bc = X + (size_t)c * D4 + sub;
            float4 a[4], b[4];
            #pragma unroll
            for (int k = 0; k < 4; k++) a[k] = __ldg(Ar + 8 * k);
            #pragma unroll
            for (int k = 0; k < 4; k++) b[k] = __ldg(Bc + 8 * k);

            int en = e + ngroups;
            int rn = 0, cn = 0;
            if (en < E) { rn = __ldg(&ei[en]); cn = __ldg(&ei[E + en]); }

            float s = 0.f, nr = 0.f;
            #pragma unroll
            for (int k = 0; k < 4; k++) {
                s  += a[k].x*b[k].x + a[k].y*b[k].y + a[k].z*b[k].z + a[k].w*b[k].w;
                nr += a[k].x*a[k].x + a[k].y*a[k].y + a[k].z*a[k].z + a[k].w*a[k].w;
            }
            #pragma unroll
            for (int o = 4; o > 0; o >>= 1) {
                s  += __shfl_xor_sync(0xFFFFFFFFu, s,  o);
                nr += __shfl_xor_sync(0xFFFFFFFFu, nr, o);
            }
            if (sub == 0) {
                g_dot[e] = s;
                // csum_c = rinv_c * SUM(dot * rinv_r)  — rinv_c applied in combo2.
                // pack: low bits carry dot*rinv_r sum, 2^20 steps count degree.
                double v = (double)(s * rsqrtf(nr)) + DEG_BIAS;
                atomicAdd(&g_cdpack[c], v);
            }
            e = en; r = rn; c = cn;
        }
    } else if (bid == NBE) {
        if (threadIdx.x < 32) setup_body(ps, pd, po, threadIdx.x);
    } else {
        int w    = ((bid - NBE - 1) * blockDim.x + threadIdx.x) >> 5;
        int lane = threadIdx.x & 31;
        if (w >= n) return;
        float4 xv = X[(size_t)w * D4 + lane];
        float4 P0 = reinterpret_cast<const float4*>(ps)[lane];
        float4 P1 = reinterpret_cast<const float4*>(pd)[lane];
        float4 P2 = reinterpret_cast<const float4*>(po)[lane];

        float ss = xv.x*xv.x + xv.y*xv.y + xv.z*xv.z + xv.w*xv.w;
        float d0 = xv.x*P0.x + xv.y*P0.y + xv.z*P0.z + xv.w*P0.w;
        float d1 = xv.x*P1.x + xv.y*P1.y + xv.z*P1.z + xv.w*P1.w;
        float d2 = xv.x*P2.x + xv.y*P2.y + xv.z*P2.z + xv.w*P2.w;
        #pragma unroll
        for (int o = 16; o > 0; o >>= 1) {
            ss += __shfl_xor_sync(0xFFFFFFFFu, ss, o);
            d0 += __shfl_xor_sync(0xFFFFFFFFu, d0, o);
            d1 += __shfl_xor_sync(0xFFFFFFFFu, d1, o);
            d2 += __shfl_xor_sync(0xFFFFFFFFu, d2, o);
        }
        if (lane == 0) g_rec[w][1] = make_float4(d0, d1, d2, ss);
    }
}

// ---------- combo2 (thread/node): decode scatter, fold combo + norms into record ----------
__global__ void combo2_kernel(int n) {
    int i = blockIdx.x * blockDim.x + threadIdx.x;
    if (i >= n) return;
    double t  = g_cdpack[i];
    float4 A  = g_rec[i][1];   // (d0, d1, d2, ||x||^2)

    double degd = floor(t * (1.0 / DEG_BIAS) + 0.5);
    float  deg  = (float)degd;
    float  csum_scaled = (float)(t - degd * DEG_BIAS);   // = SUM(dot * rinv_r)
    float  rinv_c = rsqrtf(A.w);
    float  csum = csum_scaled * rinv_c;

    bool msim = (deg > 0.f) && ((csum / deg) <= SIM_THR);
    bool mdeg = (deg <= DEG_THR);
    int c = (int)msim | ((int)mdeg << 1);

    float4 Wc = *reinterpret_cast<const float4*>(&g_W[c][0]);
    float4 Gv = *reinterpret_cast<const float4*>(&g_GV[c][0]);
    float xdd = Wc.x*A.x + Wc.y*A.y + Wc.z*A.z;
    float nn2 = A.w + 2.0f * xdd + g_GC[c][c];
    float s = 1.0f / fmaxf(sqrtf(fmaxf(nn2, 0.f)), EPSV);

    // H = s*(d + 0.5*G*W[c]),  U = s*W[c]
    g_rec[i][0] = make_float4(s * (A.x + 0.5f * Gv.x),
                              s * (A.y + 0.5f * Gv.y),
                              s * (A.z + 0.5f * Gv.z), s);
    g_rec[i][1] = make_float4(s * Wc.x, s * Wc.y, s * Wc.z, __int_as_float(c));
}

// ---------- K2 finish: node write (MLP4) | edge2 (pure gather+FMA) ----------
__global__ void finish_kernel(const float* __restrict__ x,
                              const int* __restrict__ ei,
                              float* __restrict__ out,
                              float* __restrict__ keep,
                              int n, int E, int NBn) {
    if ((int)blockIdx.x < NBn) {
        int tid  = threadIdx.x;
        int node = blockIdx.x * 32 + (tid >> 3);
        if (node >= n) return;
        int j = tid & 7;
        int idx = __float_as_int(g_rec[node][1].w);
        const float4* Xr = reinterpret_cast<const float4*>(x) + (size_t)node * D4;
        float4 xv0 = __ldcs(Xr + j);
        float4 xv1 = __ldcs(Xr + j + 8);
        float4 xv2 = __ldcs(Xr + j + 16);
        float4 xv3 = __ldcs(Xr + j + 24);
        float4 dl0 = g_delta[idx][j];
        float4 dl1 = g_delta[idx][j + 8];
        float4 dl2 = g_delta[idx][j + 16];
        float4 dl3 = g_delta[idx][j + 24];
        xv0.x += dl0.x; xv0.y += dl0.y; xv0.z += dl0.z; xv0.w += dl0.w;
        xv1.x += dl1.x; xv1.y += dl1.y; xv1.z += dl1.z; xv1.w += dl1.w;
        xv2.x += dl2.x; xv2.y += dl2.y; xv2.z += dl2.z; xv2.w += dl2.w;
        xv3.x += dl3.x; xv3.y += dl3.y; xv3.z += dl3.z; xv3.w += dl3.w;
        float4* Or = reinterpret_cast<float4*>(out) + (size_t)node * D4;
        __stcs(Or + j,      xv0);
        __stcs(Or + j + 8,  xv1);
        __stcs(Or + j + 16, xv2);
        __stcs(Or + j + 24, xv3);
    } else {
        // ---- edge2: 2 edges/thread; cos = (sr*sc)*dot + Hr·Uc + Hc·Ur ----
        int t  = (blockIdx.x - NBn) * blockDim.x + threadIdx.x;
        int e0 = t * 2;
        int e1 = e0 + 1;
        if (e0 >= E) return;
        bool has1 = (e1 < E);

        int r0 = __ldg(&ei[e0]);
        int c0 = __ldg(&ei[E + e0]);
        int r1 = has1 ? __ldg(&ei[e1]) : r0;
        int c1 = has1 ? __ldg(&ei[E + e1]) : c0;
        float dt0 = g_dot[e0];
        float dt1 = has1 ? g_dot[e1] : 0.f;

        float4 Hr0 = g_rec[r0][0], Ur0 = g_rec[r0][1];
        float4 Hc0 = g_rec[c0][0], Uc0 = g_rec[c0][1];
        float4 Hr1 = g_rec[r1][0], Ur1 = g_rec[r1][1];
        float4 Hc1 = g_rec[c1][0], Uc1 = g_rec[c1][1];

        float cos0 = (Hr0.w * Hc0.w) * dt0
                   + Hr0.x*Uc0.x + Hr0.y*Uc0.y + Hr0.z*Uc0.z
                   + Hc0.x*Ur0.x + Hc0.y*Ur0.y + Hc0.z*Ur0.z;
        keep[e0] = (cos0 >= PT_THR) ? 1.0f : 0.0f;
        if (has1) {
            float cos1 = (Hr1.w * Hc1.w) * dt1
                       + Hr1.x*Uc1.x + Hr1.y*Uc1.y + Hr1.z*Uc1.z
                       + Hc1.x*Ur1.x + Hc1.y*Ur1.y + Hc1.z*Ur1.z;
            keep[e1] = (cos1 >= PT_THR) ? 1.0f : 0.0f;
        }
    }
}

extern "C" void kernel_launch(void* const* d_in, const int* in_sizes, int n_in,
                              void* d_out, int out_size) {
    const float* x  = (const float*)d_in[0];
    const int*   ei = (const int*)d_in[1];
    const float* ps = (const float*)d_in[2];
    const float* pd = (const float*)d_in[3];
    const float* po = (const float*)d_in[4];
    float* out = (float*)d_out;

    int N = in_sizes[0] / D;
    int E = in_sizes[1] / 2;

    static void* pack_ptr = nullptr;
    if (!pack_ptr) cudaGetSymbolAddress(&pack_ptr, g_cdpack);
    cudaMemsetAsync(pack_ptr, 0, (size_t)N * sizeof(double));

    int NBa = (N + 7) / 8;
    big_kernel<<<NBE + 1 + NBa, 256>>>(x, ei, ps, pd, po, N, E);

    combo2_kernel<<<(N + 255) / 256, 256>>>(N);

    int NBn = (N + 31) / 32;
    bool do_keep = ((long long)out_size >= (long long)N * D + E);
    int NBe2 = do_keep ? ((E + 1) / 2 + 255) / 256 : 0;
    float* keep = out + (size_t)N * D;
    finish_kernel<<<NBn + NBe2, 256>>>(x, ei, out, keep, N, E, NBn);
}

// round 12
// speedup vs baseline: 1.0338x; 1.0270x over previous
#include <cuda_runtime.h>
#include <cuda_bf16.h>

// RobustPrompt_I: graph prompt + edge pruning
//  in: x[N,128] f32, edge_index[2,E] i32, p_sim[1,128], p_deg[1,128], p_other[1,128]
//  out: x_new[N,128] f32  ++  keep[E] (0/1 as f32)

#define D        128
#define D4       32
#define NCAP     131072
#define ECAP     1048576
#define SIM_THR  0.2f
#define DEG_THR  3.0f
#define PT_THR   0.1f
#define EPSV     1e-8f

#define NBE      2048        // persistent edge blocks in big_kernel

__device__ float2 g_cd[NCAP];      // (SUM(dot*rinv_r), deg) per node — dense atomics
__device__ float4 g_A0[NCAP];      // (d0, d1, d2, ||x||^2) from node stats
__device__ float4 g_rec16[NCAP];   // (H0, H1, H2, s[mantissa LSBs = combo])
__device__ float  g_dot[ECAP];     // raw dot(x_r, x_c) per edge
__device__ float  g_W[4][4];       // combo -> weight triple (row=float4)
__device__ float  g_GC[4][4];      // delta_a · delta_b LUT
__device__ float  g_GV[4][4];      // G · W[c] per combo (row=float4)
__device__ float4 g_delta[4][D4];  // the 4 possible delta rows

// ---------- setup body (1 warp): nz flags, Gram, weights, delta rows, LUTs ----------
__device__ __forceinline__ void setup_body(const float* __restrict__ ps,
                                           const float* __restrict__ pd,
                                           const float* __restrict__ po,
                                           int lane) {
    unsigned full = 0xFFFFFFFFu;
    float4 P[3];
    P[0] = reinterpret_cast<const float4*>(ps)[lane];
    P[1] = reinterpret_cast<const float4*>(pd)[lane];
    P[2] = reinterpret_cast<const float4*>(po)[lane];

    int nz[3];
    #pragma unroll
    for (int k = 0; k < 3; k++) {
        bool z = (P[k].x != 0.f) & (P[k].y != 0.f) & (P[k].z != 0.f) & (P[k].w != 0.f);
        nz[k] = __all_sync(full, z);
    }
    float G[3][3];
    #pragma unroll
    for (int a = 0; a < 3; a++)
        #pragma unroll
        for (int b = 0; b < 3; b++) {
            float s = P[a].x * P[b].x + P[a].y * P[b].y + P[a].z * P[b].z + P[a].w * P[b].w;
            #pragma unroll
            for (int o = 16; o > 0; o >>= 1) s += __shfl_xor_sync(full, s, o);
            G[a][b] = s;
        }
    float W[4][3];
    #pragma unroll
    for (int idx = 0; idx < 4; idx++) {
        int msim = idx & 1, mdeg = (idx >> 1) & 1, moth = (idx == 0);
        int plen = msim * nz[0] + mdeg * nz[1] + moth * nz[2];
        float inv = (plen > 0) ? (1.0f / (float)plen) : 0.0f;
        W[idx][0] = (float)msim * inv;
        W[idx][1] = (float)mdeg * inv;
        W[idx][2] = (float)moth * inv;
        float4 dl;
        dl.x = W[idx][0]*P[0].x + W[idx][1]*P[1].x + W[idx][2]*P[2].x;
        dl.y = W[idx][0]*P[0].y + W[idx][1]*P[1].y + W[idx][2]*P[2].y;
        dl.z = W[idx][0]*P[0].z + W[idx][1]*P[1].z + W[idx][2]*P[2].z;
        dl.w = W[idx][0]*P[0].w + W[idx][1]*P[1].w + W[idx][2]*P[2].w;
        g_delta[idx][lane] = dl;
    }
    if (lane == 0) {
        for (int idx = 0; idx < 4; idx++) {
            g_W[idx][0] = W[idx][0]; g_W[idx][1] = W[idx][1];
            g_W[idx][2] = W[idx][2]; g_W[idx][3] = 0.f;
            for (int k = 0; k < 3; k++)
                g_GV[idx][k] = G[k][0]*W[idx][0] + G[k][1]*W[idx][1] + G[k][2]*W[idx][2];
            g_GV[idx][3] = 0.f;
        }
        for (int a = 0; a < 4; a++)
            for (int b = 0; b < 4; b++) {
                float s = 0.f;
                for (int k = 0; k < 3; k++)
                    for (int j = 0; j < 3; j++)
                        s += W[a][k] * G[k][j] * W[b][j];
                g_GC[a][b] = s;
            }
    }
}

// ---------- K1: edges (dot + row-r norm + dense float atomics) | setup | node stats ----------
__global__ void big_kernel(const float* __restrict__ x,
                           const int* __restrict__ ei,
                           const float* __restrict__ ps,
                           const float* __restrict__ pd,
                           const float* __restrict__ po,
                           int n, int E) {
    const float4* X = reinterpret_cast<const float4*>(x);
    int bid = blockIdx.x;
    if (bid < NBE) {
        int sub     = threadIdx.x & 7;
        int group   = bid * 32 + (threadIdx.x >> 3);
        int ngroups = NBE * 32;

        int e = group;
        int r = 0, c = 0;
        if (e < E) { r = __ldg(&ei[e]); c = __ldg(&ei[E + e]); }
        while (e < E) {
            const float4* Ar = X + (size_t)r * D4 + sub;
            const float4* Bc = X + (size_t)c * D4 + sub;
            float4 a[4], b[4];
            #pragma unroll
            for (int k = 0; k < 4; k++) a[k] = __ldg(Ar + 8 * k);
            #pragma unroll
            for (int k = 0; k < 4; k++) b[k] = __ldg(Bc + 8 * k);

            int en = e + ngroups;
            int rn = 0, cn = 0;
            if (en < E) { rn = __ldg(&ei[en]); cn = __ldg(&ei[E + en]); }

            float s = 0.f, nr = 0.f;
            #pragma unroll
            for (int k = 0; k < 4; k++) {
                s  += a[k].x*b[k].x + a[k].y*b[k].y + a[k].z*b[k].z + a[k].w*b[k].w;
                nr += a[k].x*a[k].x + a[k].y*a[k].y + a[k].z*a[k].z + a[k].w*a[k].w;
            }
            #pragma unroll
            for (int o = 4; o > 0; o >>= 1) {
                s  += __shfl_xor_sync(0xFFFFFFFFu, s,  o);
                nr += __shfl_xor_sync(0xFFFFFFFFu, nr, o);
            }
            if (sub == 0) {
                g_dot[e] = s;
                // csum_c = rinv_c * SUM(dot * rinv_r); rinv_c applied in combo2
                atomicAdd(&g_cd[c].x, s * rsqrtf(nr));
                atomicAdd(&g_cd[c].y, 1.0f);
            }
            e = en; r = rn; c = cn;
        }
    } else if (bid == NBE) {
        if (threadIdx.x < 32) setup_body(ps, pd, po, threadIdx.x);
    } else {
        int w    = ((bid - NBE - 1) * blockDim.x + threadIdx.x) >> 5;
        int lane = threadIdx.x & 31;
        if (w >= n) return;
        float4 xv = X[(size_t)w * D4 + lane];
        float4 P0 = reinterpret_cast<const float4*>(ps)[lane];
        float4 P1 = reinterpret_cast<const float4*>(pd)[lane];
        float4 P2 = reinterpret_cast<const float4*>(po)[lane];

        float ss = xv.x*xv.x + xv.y*xv.y + xv.z*xv.z + xv.w*xv.w;
        float d0 = xv.x*P0.x + xv.y*P0.y + xv.z*P0.z + xv.w*P0.w;
        float d1 = xv.x*P1.x + xv.y*P1.y + xv.z*P1.z + xv.w*P1.w;
        float d2 = xv.x*P2.x + xv.y*P2.y + xv.z*P2.z + xv.w*P2.w;
        #pragma unroll
        for (int o = 16; o > 0; o >>= 1) {
            ss += __shfl_xor_sync(0xFFFFFFFFu, ss, o);
            d0 += __shfl_xor_sync(0xFFFFFFFFu, d0, o);
            d1 += __shfl_xor_sync(0xFFFFFFFFu, d1, o);
            d2 += __shfl_xor_sync(0xFFFFFFFFu, d2, o);
        }
        if (lane == 0) g_A0[w] = make_float4(d0, d1, d2, ss);
    }
}

// ---------- combo2 (thread/node): fold combo + norms into 16B record ----------
__global__ void combo2_kernel(int n) {
    int i = blockIdx.x * blockDim.x + threadIdx.x;
    if (i >= n) return;
    float2 cd = g_cd[i];       // (SUM(dot*rinv_r), deg)
    float4 A  = g_A0[i];       // (d0, d1, d2, ||x||^2)

    float rinv_c = rsqrtf(A.w);
    float csum = cd.x * rinv_c;
    float deg  = cd.y;

    bool msim = (deg > 0.f) && ((csum / deg) <= SIM_THR);
    bool mdeg = (deg <= DEG_THR);
    int c = (int)msim | ((int)mdeg << 1);

    float4 Wc = *reinterpret_cast<const float4*>(&g_W[c][0]);
    float4 Gv = *reinterpret_cast<const float4*>(&g_GV[c][0]);
    float xdd = Wc.x*A.x + Wc.y*A.y + Wc.z*A.z;
    float nn2 = A.w + 2.0f * xdd + g_GC[c][c];
    float s = 1.0f / fmaxf(sqrtf(fmaxf(nn2, 0.f)), EPSV);

    // pack combo into the 2 LSBs of s's mantissa (<=2.4e-7 relative perturbation)
    unsigned su = (__float_as_uint(s) & ~3u) | (unsigned)c;
    float sp = __uint_as_float(su);

    // H = s*(d + 0.5*G*W[c])
    g_rec16[i] = make_float4(sp * (A.x + 0.5f * Gv.x),
                             sp * (A.y + 0.5f * Gv.y),
                             sp * (A.z + 0.5f * Gv.z), sp);
}

// ---------- K2 finish: node write (MLP4) | edge2 (1 LDG.128/endpoint) ----------
__global__ void finish_kernel(const float* __restrict__ x,
                              const int* __restrict__ ei,
                              float* __restrict__ out,
                              float* __restrict__ keep,
                              int n, int E, int NBn) {
    if ((int)blockIdx.x < NBn) {
        int tid  = threadIdx.x;
        int node = blockIdx.x * 32 + (tid >> 3);
        if (node >= n) return;
        int j = tid & 7;
        int idx = (int)(__float_as_uint(g_rec16[node].w) & 3u);
        const float4* Xr = reinterpret_cast<const float4*>(x) + (size_t)node * D4;
        float4 xv0 = __ldcs(Xr + j);
        float4 xv1 = __ldcs(Xr + j + 8);
        float4 xv2 = __ldcs(Xr + j + 16);
        float4 xv3 = __ldcs(Xr + j + 24);
        float4 dl0 = g_delta[idx][j];
        float4 dl1 = g_delta[idx][j + 8];
        float4 dl2 = g_delta[idx][j + 16];
        float4 dl3 = g_delta[idx][j + 24];
        xv0.x += dl0.x; xv0.y += dl0.y; xv0.z += dl0.z; xv0.w += dl0.w;
        xv1.x += dl1.x; xv1.y += dl1.y; xv1.z += dl1.z; xv1.w += dl1.w;
        xv2.x += dl2.x; xv2.y += dl2.y; xv2.z += dl2.z; xv2.w += dl2.w;
        xv3.x += dl3.x; xv3.y += dl3.y; xv3.z += dl3.z; xv3.w += dl3.w;
        float4* Or = reinterpret_cast<float4*>(out) + (size_t)node * D4;
        __stcs(Or + j,      xv0);
        __stcs(Or + j + 8,  xv1);
        __stcs(Or + j + 16, xv2);
        __stcs(Or + j + 24, xv3);
    } else {
        // ---- edge2: 2 edges/thread; one 16B record per endpoint ----
        // cos = (sr*sc)*dot + sc*(Hr·W[cc]) + sr*(Hc·W[cr])
        int t  = (blockIdx.x - NBn) * blockDim.x + threadIdx.x;
        int e0 = t * 2;
        int e1 = e0 + 1;
        if (e0 >= E) return;
        bool has1 = (e1 < E);

        int r0 = __ldg(&ei[e0]);
        int c0 = __ldg(&ei[E + e0]);
        int r1 = has1 ? __ldg(&ei[e1]) : r0;
        int c1 = has1 ? __ldg(&ei[E + e1]) : c0;
        float dt0 = g_dot[e0];
        float dt1 = has1 ? g_dot[e1] : 0.f;

        float4 R0 = g_rec16[r0], C0 = g_rec16[c0];
        float4 R1 = g_rec16[r1], C1 = g_rec16[c1];

        int cr0 = (int)(__float_as_uint(R0.w) & 3u);
        int cc0 = (int)(__float_as_uint(C0.w) & 3u);
        int cr1 = (int)(__float_as_uint(R1.w) & 3u);
        int cc1 = (int)(__float_as_uint(C1.w) & 3u);

        float4 Wr0 = *reinterpret_cast<const float4*>(&g_W[cr0][0]);
        float4 Wc0 = *reinterpret_cast<const float4*>(&g_W[cc0][0]);
        float4 Wr1 = *reinterpret_cast<const float4*>(&g_W[cr1][0]);
        float4 Wc1 = *reinterpret_cast<const float4*>(&g_W[cc1][0]);

        float cos0 = (R0.w * C0.w) * dt0
                   + C0.w * (R0.x*Wc0.x + R0.y*Wc0.y + R0.z*Wc0.z)
                   + R0.w * (C0.x*Wr0.x + C0.y*Wr0.y + C0.z*Wr0.z);
        keep[e0] = (cos0 >= PT_THR) ? 1.0f : 0.0f;
        if (has1) {
            float cos1 = (R1.w * C1.w) * dt1
                       + C1.w * (R1.x*Wc1.x + R1.y*Wc1.y + R1.z*Wc1.z)
                       + R1.w * (C1.x*Wr1.x + C1.y*Wr1.y + C1.z*Wr1.z);
            keep[e1] = (cos1 >= PT_THR) ? 1.0f : 0.0f;
        }
    }
}

extern "C" void kernel_launch(void* const* d_in, const int* in_sizes, int n_in,
                              void* d_out, int out_size) {
    const float* x  = (const float*)d_in[0];
    const int*   ei = (const int*)d_in[1];
    const float* ps = (const float*)d_in[2];
    const float* pd = (const float*)d_in[3];
    const float* po = (const float*)d_in[4];
    float* out = (float*)d_out;

    int N = in_sizes[0] / D;
    int E = in_sizes[1] / 2;

    static void* cd_ptr = nullptr;
    if (!cd_ptr) cudaGetSymbolAddress(&cd_ptr, g_cd);
    cudaMemsetAsync(cd_ptr, 0, (size_t)N * sizeof(float2));

    int NBa = (N + 7) / 8;
    big_kernel<<<NBE + 1 + NBa, 256>>>(x, ei, ps, pd, po, N, E);

    combo2_kernel<<<(N + 255) / 256, 256>>>(N);

    int NBn = (N + 31) / 32;
    bool do_keep = ((long long)out_size >= (long long)N * D + E);
    int NBe2 = do_keep ? ((E + 1) / 2 + 255) / 256 : 0;
    float* keep = out + (size_t)N * D;
    finish_kernel<<<NBn + NBe2, 256>>>(x, ei, out, keep, N, E, NBn);
}